// round 11
// baseline (speedup 1.0000x reference)
#include <cuda_runtime.h>
#include <cuda_fp16.h>
#include <math.h>

// Problem dims (fixed by the reference)
#define Bq 32
#define Tq 2048
#define Dq 512
#define Uq 512

// Scratch (no device allocation allowed -> __device__ globals)
__device__ float  g_uh[Bq * Uq];      // hidden@Uk + Ub + Wb  (per b,u bias)
__device__ float  g_logits[Bq * Tq];  // pre-softmax logits (Vb dropped: softmax-invariant)
__device__ __half g_wkh[Uq * Dq];     // Wk^T as half, [u][d] (B operand, K-contiguous)

// ---------------- helpers ----------------
__device__ __forceinline__ unsigned smem_u32(const void* p) {
    unsigned a;
    asm("{ .reg .u64 t; cvta.to.shared.u64 t, %1; cvt.u32.u64 %0, t; }" : "=r"(a) : "l"(p));
    return a;
}
__device__ __forceinline__ void cpasync16(unsigned dst, const void* src) {
    asm volatile("cp.async.cg.shared.global [%0], [%1], 16;" :: "r"(dst), "l"(src));
}
__device__ __forceinline__ unsigned h2tanh(unsigned x) {   // MUFU.TANH on 2 halves
    unsigned r;
    asm("tanh.approx.f16x2 %0, %1;" : "=r"(r) : "r"(x));
    return r;
}
__device__ __forceinline__ unsigned h2add(unsigned a, unsigned b) {
    unsigned r;
    asm("add.f16x2 %0, %1, %2;" : "=r"(r) : "r"(a), "r"(b));
    return r;
}
__device__ __forceinline__ void ldmx4(unsigned* r, unsigned addr) {
    asm volatile("ldmatrix.sync.aligned.m8n8.x4.shared.b16 {%0,%1,%2,%3}, [%4];"
                 : "=r"(r[0]), "=r"(r[1]), "=r"(r[2]), "=r"(r[3]) : "r"(addr));
}
// fp16-accumulate MMA: C/D are 2 regs of f16x2
__device__ __forceinline__ void mma_f16a(unsigned& c0, unsigned& c1, const unsigned* a,
                                         unsigned b0, unsigned b1) {
    asm volatile(
        "mma.sync.aligned.m16n8k16.row.col.f16.f16.f16.f16 "
        "{%0,%1}, {%2,%3,%4,%5}, {%6,%7}, {%0,%1};"
        : "+r"(c0), "+r"(c1)
        : "r"(a[0]), "r"(a[1]), "r"(a[2]), "r"(a[3]), "r"(b0), "r"(b1));
}

// ---------------------------------------------------------------------------
// Kernel 0 (merged prep): blocks [0,64) compute g_uh; blocks [64,320) build
// g_wkh (transpose + f32->f16). One launch instead of two.
// ---------------------------------------------------------------------------
__global__ __launch_bounds__(256)
void prep_kernel(const float* __restrict__ hidden,
                 const float* __restrict__ Uk,
                 const float* __restrict__ Ub,
                 const float* __restrict__ Wb,
                 const float* __restrict__ Wk) {
    __shared__ float t[32][33];
    const int bx = blockIdx.x;
    const int tid = threadIdx.x;
    if (bx < 64) {
        // uh: b = bx>>1, u = (bx&1)*256 + tid
        const int b = bx >> 1;
        const int u = (bx & 1) * 256 + tid;
        float acc = Ub[u] + Wb[u];
        const float* h = hidden + b * 512;
        #pragma unroll 8
        for (int k = 0; k < 512; k++)
            acc = fmaf(h[k], Uk[k * Uq + u], acc);
        g_uh[b * Uq + u] = acc;
    } else {
        // wkh transpose tile
        const int tt = bx - 64;                 // 0..255
        const int bu = (tt & 15) * 32, bd = (tt >> 4) * 32;
        const int tx = tid & 31, ty = tid >> 5; // 32 x 8
        #pragma unroll
        for (int i = 0; i < 32; i += 8)
            t[ty + i][tx] = Wk[(bd + ty + i) * Uq + bu + tx];   // t[d][u]
        __syncthreads();
        #pragma unroll
        for (int i = 0; i < 32; i += 8)
            g_wkh[(bu + ty + i) * Dq + bd + tx] = __float2half(t[tx][ty + i]);
    }
}

// ---------------------------------------------------------------------------
// Kernel 1 (hot): R10 warp-level structure EXACTLY, with BM=128 / 512 threads:
// 16 warps = 2 (wm) x 8 (wn); each warp m64 x n64, f16 acc (64 regs).
// Same warps/SMSP as R10 (4), but per-CTA B amortization doubled:
// B L2 traffic 512MB -> 256MB; fillB/storeA overhead per MMA halved.
// ---------------------------------------------------------------------------
#define BM 128
#define NT 512
#define KS 32
#define NSTG (Dq / KS)          // 16 stages, 2 k16-steps each
#define ROWB 80                 // padded row pitch in bytes (40 halves)
#define ABUF (BM * ROWB)        // 10240
#define BBUF (Uq * ROWB)        // 40960

#define SM_A    0                       // 2 x ABUF = 20480
#define SM_B    (2 * ABUF)              // 2 x BBUF = 81920
#define SM_UH   (SM_B + 2 * BBUF)       // 102400 (256 half2 = 1KB used)
#define SM_VK   (SM_UH + 2048)          // 104448 (512 floats)
#define SM_RED  (SM_VK + 2048)          // 106496 (128 floats)
#define SM_TOT  (SM_RED + 512 + 128)    // 107136 bytes (occ 1)

__global__ __launch_bounds__(NT, 1)
void logits_kernel(const float* __restrict__ features,
                   const float* __restrict__ Vk) {
    extern __shared__ char smem[];
    const unsigned sb = smem_u32(smem);
    const int tid = threadIdx.x, lane = tid & 31, wid = tid >> 5;
    const int wm  = wid >> 3;                   // 0..1  (M half)
    const int n0w = (wid & 7) * 64;             // warp's N offset
    const long row0 = (long)blockIdx.x * BM;
    const int b = (int)(row0 >> 11);

    unsigned* uh2s = (unsigned*)(smem + SM_UH);     // 256 x half2
    float*    vks  = (float*)(smem + SM_VK);
    float*    red  = (float*)(smem + SM_RED);

    if (tid < 256) {
        __half2 h = __floats2half2_rn(g_uh[b * Uq + 2 * tid], g_uh[b * Uq + 2 * tid + 1]);
        uh2s[tid] = *reinterpret_cast<unsigned*>(&h);
    }
    vks[tid] = Vk[tid];
    if (tid < BM) red[tid] = 0.f;

    const int ar_r   = tid >> 2;                // A row 0..127
    const int ar_k4a = (tid & 3) * 2;           // two consecutive float4 slots
    const int lr = lane & 7, sect = lane >> 3;  // ldmatrix lane addressing

    unsigned acc16[4][8][2];                    // f16x2 accumulators (64 regs)
    #pragma unroll
    for (int mi = 0; mi < 4; mi++)
        #pragma unroll
        for (int nt = 0; nt < 8; nt++) { acc16[mi][nt][0] = 0u; acc16[mi][nt][1] = 0u; }

    float4 ar[2][2];    // A global->reg double buffer

    auto loadA = [&](int s, int pb) {
        #pragma unroll
        for (int i = 0; i < 2; i++)
            ar[pb][i] = *reinterpret_cast<const float4*>(
                features + (row0 + ar_r) * Dq + s * KS + (ar_k4a + i) * 4);
    };
    auto storeA = [&](int buf, int pb) {
        #pragma unroll
        for (int i = 0; i < 2; i++) {
            float4 v = ar[pb][i];
            __half2 h0 = __floats2half2_rn(v.x, v.y);
            __half2 h1 = __floats2half2_rn(v.z, v.w);
            uint2 u = make_uint2(*reinterpret_cast<unsigned*>(&h0),
                                 *reinterpret_cast<unsigned*>(&h1));
            *reinterpret_cast<uint2*>(smem + SM_A + buf * ABUF +
                                      ar_r * ROWB + (ar_k4a + i) * 8) = u;
        }
    };
    auto fillB = [&](int s, int buf) {
        const unsigned bb = sb + SM_B + buf * BBUF;
        #pragma unroll
        for (int i = 0; i < 4; i++) {
            int idx = tid + i * NT;             // 0..2047
            int n = idx >> 2, c = idx & 3;
            cpasync16(bb + (unsigned)(n * ROWB + c * 16),
                      g_wkh + n * Dq + s * KS + c * 8);
        }
    };

    loadA(0, 0);
    fillB(0, 0);
    asm volatile("cp.async.commit_group;");

    for (int s = 0; s < NSTG; s++) {
        const int buf = s & 1;
        if (s + 1 < NSTG) {
            fillB(s + 1, 1 - buf);
            asm volatile("cp.async.commit_group;");
            loadA(s + 1, 1 - buf);
        }
        storeA(buf, buf);
        if (s + 1 < NSTG) asm volatile("cp.async.wait_group 1;");
        else              asm volatile("cp.async.wait_group 0;");
        __syncthreads();

        const unsigned ab = sb + SM_A + buf * ABUF;
        const unsigned bb = sb + SM_B + buf * BBUF;
        #pragma unroll
        for (int k16 = 0; k16 < 2; k16++) {
            const int kb = k16 * 16;            // halves offset within stage row
            unsigned af[4][4], bf[4][4];
            // A frags: (m0:8,k0:8),(m8:16,k0:8),(m0:8,k8:16),(m8:16,k8:16)
            #pragma unroll
            for (int mi = 0; mi < 4; mi++)
                ldmx4(af[mi], ab + (unsigned)((wm * 64 + mi * 16 + (sect & 1) * 8 + lr) * ROWB
                                              + (kb + (sect >> 1) * 8) * 2));
            // B frags: (n0:8,k0:8),(n0:8,k8:16),(n8:16,k0:8),(n8:16,k8:16)
            #pragma unroll
            for (int nj = 0; nj < 4; nj++)
                ldmx4(bf[nj], bb + (unsigned)((n0w + nj * 16 + (sect >> 1) * 8 + lr) * ROWB
                                              + (kb + (sect & 1) * 8) * 2));
            #pragma unroll
            for (int mi = 0; mi < 4; mi++)
                #pragma unroll
                for (int nj = 0; nj < 4; nj++) {
                    mma_f16a(acc16[mi][2 * nj][0],     acc16[mi][2 * nj][1],
                             af[mi], bf[nj][0], bf[nj][1]);
                    mma_f16a(acc16[mi][2 * nj + 1][0], acc16[mi][2 * nj + 1][1],
                             af[mi], bf[nj][2], bf[nj][3]);
                }
        }
        __syncthreads();
    }

    // ---- epilogue: x = acc + uh (f16x2); tanh (f16x2); rowsum += Vk * tanh ----
    const int g = lane >> 2, t = lane & 3;
    float rs[8];
    #pragma unroll
    for (int i = 0; i < 8; i++) rs[i] = 0.f;
    #pragma unroll
    for (int mi = 0; mi < 4; mi++)
        #pragma unroll
        for (int nt = 0; nt < 8; nt++) {
            const int n = n0w + nt * 8 + 2 * t;
            unsigned uh2 = uh2s[n >> 1];
            float vk0 = vks[n], vk1 = vks[n + 1];
            unsigned t0 = h2tanh(h2add(acc16[mi][nt][0], uh2));
            float2 f0 = __half22float2(*reinterpret_cast<__half2*>(&t0));
            rs[mi * 2]     = fmaf(vk0, f0.x, fmaf(vk1, f0.y, rs[mi * 2]));
            unsigned t1 = h2tanh(h2add(acc16[mi][nt][1], uh2));
            float2 f1 = __half22float2(*reinterpret_cast<__half2*>(&t1));
            rs[mi * 2 + 1] = fmaf(vk0, f1.x, fmaf(vk1, f1.y, rs[mi * 2 + 1]));
        }
    #pragma unroll
    for (int i = 0; i < 8; i++) {
        rs[i] += __shfl_xor_sync(0xffffffffu, rs[i], 1);
        rs[i] += __shfl_xor_sync(0xffffffffu, rs[i], 2);
    }
    if (t == 0) {
        #pragma unroll
        for (int mi = 0; mi < 4; mi++) {
            atomicAdd(&red[wm * 64 + mi * 16 + g],     rs[mi * 2]);
            atomicAdd(&red[wm * 64 + mi * 16 + 8 + g], rs[mi * 2 + 1]);
        }
    }
    __syncthreads();
    if (tid < BM) g_logits[row0 + tid] = red[tid];
}

// ---------------------------------------------------------------------------
// Kernel 2: softmax over T per batch -> weights to d_out; also zeroes ctx
// ---------------------------------------------------------------------------
__global__ void softmax_kernel(float* __restrict__ out_w, float* __restrict__ ctx) {
    const int b = blockIdx.x;
    const int tid = threadIdx.x;   // 256
    __shared__ float sm[256];
    const float* lg = g_logits + b * Tq;

    ctx[b * Dq + tid] = 0.f;
    ctx[b * Dq + 256 + tid] = 0.f;

    float mx = -1e30f;
    for (int t = tid; t < Tq; t += 256) mx = fmaxf(mx, lg[t]);
    sm[tid] = mx; __syncthreads();
    for (int s = 128; s > 0; s >>= 1) {
        if (tid < s) sm[tid] = fmaxf(sm[tid], sm[tid + s]);
        __syncthreads();
    }
    mx = sm[0]; __syncthreads();

    float sum = 0.f;
    for (int t = tid; t < Tq; t += 256) sum += expf(lg[t] - mx);
    sm[tid] = sum; __syncthreads();
    for (int s = 128; s > 0; s >>= 1) {
        if (tid < s) sm[tid] += sm[tid + s];
        __syncthreads();
    }
    float inv = 1.f / sm[0];

    for (int t = tid; t < Tq; t += 256)
        out_w[b * Tq + t] = expf(lg[t] - mx) * inv;
}

// ---------------------------------------------------------------------------
// Kernel 3: context[b,d] = sum_t w[b,t] * features[b,t,d]
// ---------------------------------------------------------------------------
#define TCHUNK 128
__global__ __launch_bounds__(256, 8)
void context_kernel(const float* __restrict__ features,
                    const float* __restrict__ w,
                    float* __restrict__ ctx) {
    __shared__ float ws[TCHUNK];
    const int b  = blockIdx.y;
    const int t0 = blockIdx.x * TCHUNK;
    const int tid = threadIdx.x;
    const int d4 = tid & 127;
    const int tp = tid >> 7;

    if (tid < TCHUNK) ws[tid] = w[b * Tq + t0 + tid];
    __syncthreads();

    const float* fb = features + (long)b * Tq * Dq + (long)t0 * Dq + d4 * 4;
    float4 acc = make_float4(0.f, 0.f, 0.f, 0.f);
    #pragma unroll 4
    for (int i = tp; i < TCHUNK; i += 2) {
        float  wt = ws[i];
        float4 v  = *reinterpret_cast<const float4*>(fb + (long)i * Dq);
        acc.x = fmaf(wt, v.x, acc.x);
        acc.y = fmaf(wt, v.y, acc.y);
        acc.z = fmaf(wt, v.z, acc.z);
        acc.w = fmaf(wt, v.w, acc.w);
    }
    float* dst = ctx + b * Dq + d4 * 4;
    atomicAdd(dst + 0, acc.x);
    atomicAdd(dst + 1, acc.y);
    atomicAdd(dst + 2, acc.z);
    atomicAdd(dst + 3, acc.w);
}

// ---------------------------------------------------------------------------
extern "C" void kernel_launch(void* const* d_in, const int* in_sizes, int n_in,
                              void* d_out, int out_size) {
    const float* features = (const float*)d_in[0];  // [B,T,D]
    const float* hidden   = (const float*)d_in[1];  // [B,H]
    const float* Wk       = (const float*)d_in[2];  // [D,U]
    const float* Wb       = (const float*)d_in[3];  // [U]
    const float* Uk       = (const float*)d_in[4];  // [H,U]
    const float* Ub       = (const float*)d_in[5];  // [U]
    const float* Vk       = (const float*)d_in[6];  // [U,1]
    // d_in[7] = Vb [1]: uniform logit shift -> softmax-invariant -> unused.

    float* out  = (float*)d_out;
    float* ctx  = out;               // context_vector [B, D]  (tuple output 0)
    float* attw = out + Bq * Dq;     // attention_weights [B, T, 1] (tuple output 1)

    cudaFuncSetAttribute(logits_kernel,
                         cudaFuncAttributeMaxDynamicSharedMemorySize, SM_TOT);

    prep_kernel<<<320, 256>>>(hidden, Uk, Ub, Wb, Wk);
    logits_kernel<<<(Bq * Tq) / BM, NT, SM_TOT>>>(features, Vk);
    softmax_kernel<<<Bq, 256>>>(attw, ctx);
    context_kernel<<<dim3(Tq / TCHUNK, Bq), 256>>>(features, attw, ctx);
}

// round 12
// speedup vs baseline: 1.1080x; 1.1080x over previous
#include <cuda_runtime.h>
#include <cuda_fp16.h>
#include <math.h>

// Problem dims (fixed by the reference)
#define Bq 32
#define Tq 2048
#define Dq 512
#define Uq 512

// Scratch (no device allocation allowed -> __device__ globals)
__device__ float  g_uh[Bq * Uq];      // hidden@Uk + Ub + Wb  (per b,u bias)
__device__ float  g_logits[Bq * Tq];  // pre-softmax logits (Vb dropped: softmax-invariant)
__device__ __half g_wkh[Uq * Dq];     // Wk^T as half, [u][d] (B operand, K-contiguous)

// ---------------- helpers ----------------
__device__ __forceinline__ unsigned smem_u32(const void* p) {
    unsigned a;
    asm("{ .reg .u64 t; cvta.to.shared.u64 t, %1; cvt.u32.u64 %0, t; }" : "=r"(a) : "l"(p));
    return a;
}
__device__ __forceinline__ void cpasync16(unsigned dst, const void* src) {
    asm volatile("cp.async.cg.shared.global [%0], [%1], 16;" :: "r"(dst), "l"(src));
}
__device__ __forceinline__ unsigned h2tanh(unsigned x) {   // MUFU.TANH on 2 halves
    unsigned r;
    asm("tanh.approx.f16x2 %0, %1;" : "=r"(r) : "r"(x));
    return r;
}
__device__ __forceinline__ unsigned h2add(unsigned a, unsigned b) {
    unsigned r;
    asm("add.f16x2 %0, %1, %2;" : "=r"(r) : "r"(a), "r"(b));
    return r;
}
__device__ __forceinline__ void ldmx4(unsigned* r, unsigned addr) {
    asm volatile("ldmatrix.sync.aligned.m8n8.x4.shared.b16 {%0,%1,%2,%3}, [%4];"
                 : "=r"(r[0]), "=r"(r[1]), "=r"(r[2]), "=r"(r[3]) : "r"(addr));
}
// fp16-accumulate MMA: C/D are 2 regs of f16x2
__device__ __forceinline__ void mma_f16a(unsigned& c0, unsigned& c1, const unsigned* a,
                                         unsigned b0, unsigned b1) {
    asm volatile(
        "mma.sync.aligned.m16n8k16.row.col.f16.f16.f16.f16 "
        "{%0,%1}, {%2,%3,%4,%5}, {%6,%7}, {%0,%1};"
        : "+r"(c0), "+r"(c1)
        : "r"(a[0]), "r"(a[1]), "r"(a[2]), "r"(a[3]), "r"(b0), "r"(b1));
}

// ---------------------------------------------------------------------------
// Kernel 0 (merged prep): blocks [0,64): g_uh + zero ctx slice;
// blocks [64,320): g_wkh transpose + f32->f16.
// ---------------------------------------------------------------------------
__global__ __launch_bounds__(256)
void prep_kernel(const float* __restrict__ hidden,
                 const float* __restrict__ Uk,
                 const float* __restrict__ Ub,
                 const float* __restrict__ Wb,
                 const float* __restrict__ Wk,
                 float* __restrict__ ctx) {
    __shared__ float t[32][33];
    const int bx = blockIdx.x;
    const int tid = threadIdx.x;
    if (bx < 64) {
        const int b = bx >> 1;
        const int u = (bx & 1) * 256 + tid;
        ctx[b * Dq + u] = 0.f;                  // zero context for this replay
        float acc = Ub[u] + Wb[u];
        const float* h = hidden + b * 512;
        #pragma unroll 8
        for (int k = 0; k < 512; k++)
            acc = fmaf(h[k], Uk[k * Uq + u], acc);
        g_uh[b * Uq + u] = acc;
    } else {
        const int tt = bx - 64;                 // 0..255
        const int bu = (tt & 15) * 32, bd = (tt >> 4) * 32;
        const int tx = tid & 31, ty = tid >> 5; // 32 x 8
        #pragma unroll
        for (int i = 0; i < 32; i += 8)
            t[ty + i][tx] = Wk[(bd + ty + i) * Uq + bu + tx];   // t[d][u]
        __syncthreads();
        #pragma unroll
        for (int i = 0; i < 32; i += 8)
            g_wkh[(bu + ty + i) * Dq + bd + tx] = __float2half(t[tx][ty + i]);
    }
}

// ---------------------------------------------------------------------------
// Kernel 1 (hot): R10 winner, verbatim. fp16-acc mma.sync m16n8k16 + ldmatrix.
// CTA: BM=64 x N=512, 8 warps (warp = m64 x n64), f16 acc (64 regs), occ 2.
// ---------------------------------------------------------------------------
#define BM 64
#define KS 32
#define NSTG (Dq / KS)          // 16 stages, 2 k16-steps each
#define ROWB 80                 // padded row pitch in bytes (40 halves)
#define ABUF (BM * ROWB)        // 5120
#define BBUF (Uq * ROWB)        // 40960

#define SM_A    0                       // 2 x ABUF = 10240
#define SM_B    10240                   // 2 x BBUF = 81920
#define SM_UH   (SM_B + 2 * BBUF)       // 92160  (256 half2 = 1KB used)
#define SM_VK   (SM_UH + 2048)          // 94208  (512 floats)
#define SM_RED  (SM_VK + 2048)          // 96256  (64 floats)
#define SM_TOT  (SM_RED + 256)          // 96512 bytes -> 2 CTAs/SM

__global__ __launch_bounds__(256, 2)
void logits_kernel(const float* __restrict__ features,
                   const float* __restrict__ Vk) {
    extern __shared__ char smem[];
    const unsigned sb = smem_u32(smem);
    const int tid = threadIdx.x, lane = tid & 31, wid = tid >> 5;
    const int n0w = wid * 64;                   // warp's N offset
    const long row0 = (long)blockIdx.x * BM;
    const int b = (int)(row0 >> 11);

    unsigned* uh2s = (unsigned*)(smem + SM_UH);     // 256 x half2
    float*    vks  = (float*)(smem + SM_VK);
    float*    red  = (float*)(smem + SM_RED);

    {
        __half2 h = __floats2half2_rn(g_uh[b * Uq + 2 * tid], g_uh[b * Uq + 2 * tid + 1]);
        uh2s[tid] = *reinterpret_cast<unsigned*>(&h);
        vks[tid] = Vk[tid];
        vks[tid + 256] = Vk[tid + 256];
    }
    if (tid < BM) red[tid] = 0.f;

    const int ar_r   = tid >> 2;                // A row 0..63
    const int ar_k4a = (tid & 3) * 2;           // two consecutive float4 slots
    const int lr = lane & 7, sect = lane >> 3;  // ldmatrix lane addressing

    unsigned acc16[4][8][2];                    // f16x2 accumulators (64 regs)
    #pragma unroll
    for (int mi = 0; mi < 4; mi++)
        #pragma unroll
        for (int nt = 0; nt < 8; nt++) { acc16[mi][nt][0] = 0u; acc16[mi][nt][1] = 0u; }

    float4 ar[2][2];    // A global->reg double buffer

    auto loadA = [&](int s, int pb) {
        #pragma unroll
        for (int i = 0; i < 2; i++)
            ar[pb][i] = *reinterpret_cast<const float4*>(
                features + (row0 + ar_r) * Dq + s * KS + (ar_k4a + i) * 4);
    };
    auto storeA = [&](int buf, int pb) {
        #pragma unroll
        for (int i = 0; i < 2; i++) {
            float4 v = ar[pb][i];
            __half2 h0 = __floats2half2_rn(v.x, v.y);
            __half2 h1 = __floats2half2_rn(v.z, v.w);
            uint2 u = make_uint2(*reinterpret_cast<unsigned*>(&h0),
                                 *reinterpret_cast<unsigned*>(&h1));
            *reinterpret_cast<uint2*>(smem + SM_A + buf * ABUF +
                                      ar_r * ROWB + (ar_k4a + i) * 8) = u;
        }
    };
    auto fillB = [&](int s, int buf) {
        const unsigned bb = sb + SM_B + buf * BBUF;
        #pragma unroll
        for (int i = 0; i < 8; i++) {
            int idx = tid + i * 256;            // 0..2047
            int n = idx >> 2, c = idx & 3;
            cpasync16(bb + (unsigned)(n * ROWB + c * 16),
                      g_wkh + n * Dq + s * KS + c * 8);
        }
    };

    loadA(0, 0);
    fillB(0, 0);
    asm volatile("cp.async.commit_group;");

    for (int s = 0; s < NSTG; s++) {
        const int buf = s & 1;
        if (s + 1 < NSTG) {
            fillB(s + 1, 1 - buf);
            asm volatile("cp.async.commit_group;");
            loadA(s + 1, 1 - buf);
        }
        storeA(buf, buf);
        if (s + 1 < NSTG) asm volatile("cp.async.wait_group 1;");
        else              asm volatile("cp.async.wait_group 0;");
        __syncthreads();

        const unsigned ab = sb + SM_A + buf * ABUF;
        const unsigned bb = sb + SM_B + buf * BBUF;
        #pragma unroll
        for (int k16 = 0; k16 < 2; k16++) {
            const int kb = k16 * 16;            // halves offset within stage row
            unsigned af[4][4], bf[4][4];
            // A frags: (m0:8,k0:8),(m8:16,k0:8),(m0:8,k8:16),(m8:16,k8:16)
            #pragma unroll
            for (int mi = 0; mi < 4; mi++)
                ldmx4(af[mi], ab + (unsigned)((mi * 16 + (sect & 1) * 8 + lr) * ROWB
                                              + (kb + (sect >> 1) * 8) * 2));
            // B frags: (n0:8,k0:8),(n0:8,k8:16),(n8:16,k0:8),(n8:16,k8:16)
            #pragma unroll
            for (int nj = 0; nj < 4; nj++)
                ldmx4(bf[nj], bb + (unsigned)((n0w + nj * 16 + (sect >> 1) * 8 + lr) * ROWB
                                              + (kb + (sect & 1) * 8) * 2));
            #pragma unroll
            for (int mi = 0; mi < 4; mi++)
                #pragma unroll
                for (int nj = 0; nj < 4; nj++) {
                    mma_f16a(acc16[mi][2 * nj][0],     acc16[mi][2 * nj][1],
                             af[mi], bf[nj][0], bf[nj][1]);
                    mma_f16a(acc16[mi][2 * nj + 1][0], acc16[mi][2 * nj + 1][1],
                             af[mi], bf[nj][2], bf[nj][3]);
                }
        }
        __syncthreads();
    }

    // ---- epilogue: x = acc + uh (f16x2); tanh (f16x2); rowsum += Vk * tanh ----
    const int g = lane >> 2, t = lane & 3;
    float rs[8];
    #pragma unroll
    for (int i = 0; i < 8; i++) rs[i] = 0.f;
    #pragma unroll
    for (int mi = 0; mi < 4; mi++)
        #pragma unroll
        for (int nt = 0; nt < 8; nt++) {
            const int n = n0w + nt * 8 + 2 * t;
            unsigned uh2 = uh2s[n >> 1];
            float vk0 = vks[n], vk1 = vks[n + 1];
            unsigned t0 = h2tanh(h2add(acc16[mi][nt][0], uh2));
            float2 f0 = __half22float2(*reinterpret_cast<__half2*>(&t0));
            rs[mi * 2]     = fmaf(vk0, f0.x, fmaf(vk1, f0.y, rs[mi * 2]));
            unsigned t1 = h2tanh(h2add(acc16[mi][nt][1], uh2));
            float2 f1 = __half22float2(*reinterpret_cast<__half2*>(&t1));
            rs[mi * 2 + 1] = fmaf(vk0, f1.x, fmaf(vk1, f1.y, rs[mi * 2 + 1]));
        }
    #pragma unroll
    for (int i = 0; i < 8; i++) {
        rs[i] += __shfl_xor_sync(0xffffffffu, rs[i], 1);
        rs[i] += __shfl_xor_sync(0xffffffffu, rs[i], 2);
    }
    if (t == 0) {
        #pragma unroll
        for (int mi = 0; mi < 4; mi++) {
            atomicAdd(&red[mi * 16 + g],     rs[mi * 2]);
            atomicAdd(&red[mi * 16 + 8 + g], rs[mi * 2 + 1]);
        }
    }
    __syncthreads();
    if (tid < BM) g_logits[row0 + tid] = red[tid];
}

// ---------------------------------------------------------------------------
// Kernel 2 (fused softmax + context): each block recomputes row softmax stats
// from g_logits (cheap L2 reads), writes its own 128 weights to d_out, then
// accumulates its context partial. Replaces separate softmax kernel.
// ---------------------------------------------------------------------------
#define TCHUNK 128
__global__ __launch_bounds__(256, 8)
void ctxw_kernel(const float* __restrict__ features,
                 float* __restrict__ out_w,
                 float* __restrict__ ctx) {
    __shared__ float sm[256];
    __shared__ float ws[TCHUNK];
    const int b  = blockIdx.y;
    const int t0 = blockIdx.x * TCHUNK;
    const int tid = threadIdx.x;
    const float* lg = g_logits + b * Tq;

    // softmax stats over the full row (8 logits per thread, kept in regs)
    float lv[8];
    float mx = -1e30f;
    #pragma unroll
    for (int i = 0; i < 8; i++) { lv[i] = lg[tid + i * 256]; mx = fmaxf(mx, lv[i]); }
    sm[tid] = mx; __syncthreads();
    for (int s = 128; s > 0; s >>= 1) {
        if (tid < s) sm[tid] = fmaxf(sm[tid], sm[tid + s]);
        __syncthreads();
    }
    mx = sm[0]; __syncthreads();
    float sum = 0.f;
    #pragma unroll
    for (int i = 0; i < 8; i++) sum += expf(lv[i] - mx);
    sm[tid] = sum; __syncthreads();
    for (int s = 128; s > 0; s >>= 1) {
        if (tid < s) sm[tid] += sm[tid + s];
        __syncthreads();
    }
    const float inv = 1.f / sm[0];

    // this block owns weights for t in [t0, t0+128)
    if (tid < TCHUNK) {
        float w = expf(lg[t0 + tid] - mx) * inv;
        ws[tid] = w;
        out_w[b * Tq + t0 + tid] = w;
    }
    __syncthreads();

    // context partial: coalesced float4 rows, MLP 8
    const int d4 = tid & 127;
    const int tp = tid >> 7;
    const float* fb = features + (long)b * Tq * Dq + (long)t0 * Dq + d4 * 4;
    float4 acc = make_float4(0.f, 0.f, 0.f, 0.f);
    #pragma unroll 8
    for (int i = tp; i < TCHUNK; i += 2) {
        float  wt = ws[i];
        float4 v  = *reinterpret_cast<const float4*>(fb + (long)i * Dq);
        acc.x = fmaf(wt, v.x, acc.x);
        acc.y = fmaf(wt, v.y, acc.y);
        acc.z = fmaf(wt, v.z, acc.z);
        acc.w = fmaf(wt, v.w, acc.w);
    }
    float* dst = ctx + b * Dq + d4 * 4;
    atomicAdd(dst + 0, acc.x);
    atomicAdd(dst + 1, acc.y);
    atomicAdd(dst + 2, acc.z);
    atomicAdd(dst + 3, acc.w);
}

// ---------------------------------------------------------------------------
extern "C" void kernel_launch(void* const* d_in, const int* in_sizes, int n_in,
                              void* d_out, int out_size) {
    const float* features = (const float*)d_in[0];  // [B,T,D]
    const float* hidden   = (const float*)d_in[1];  // [B,H]
    const float* Wk       = (const float*)d_in[2];  // [D,U]
    const float* Wb       = (const float*)d_in[3];  // [U]
    const float* Uk       = (const float*)d_in[4];  // [H,U]
    const float* Ub       = (const float*)d_in[5];  // [U]
    const float* Vk       = (const float*)d_in[6];  // [U,1]
    // d_in[7] = Vb [1]: uniform logit shift -> softmax-invariant -> unused.

    float* out  = (float*)d_out;
    float* ctx  = out;               // context_vector [B, D]  (tuple output 0)
    float* attw = out + Bq * Dq;     // attention_weights [B, T, 1] (tuple output 1)

    cudaFuncSetAttribute(logits_kernel,
                         cudaFuncAttributeMaxDynamicSharedMemorySize, SM_TOT);

    prep_kernel<<<320, 256>>>(hidden, Uk, Ub, Wb, Wk, ctx);
    logits_kernel<<<(Bq * Tq) / BM, 256, SM_TOT>>>(features, Vk);
    ctxw_kernel<<<dim3(Tq / TCHUNK, Bq), 256>>>(features, attw, ctx);
}

// round 13
// speedup vs baseline: 1.3023x; 1.1754x over previous
#include <cuda_runtime.h>
#include <cuda_fp16.h>
#include <math.h>

// Problem dims (fixed by the reference)
#define Bq 32
#define Tq 2048
#define Dq 512
#define Uq 512

// Scratch (no device allocation allowed -> __device__ globals)
__device__ float  g_uhp[8 * Bq * Uq];  // k-split partials of hidden@Uk (+bias in slice 0)
__device__ float  g_logits[Bq * Tq];   // pre-softmax logits (Vb dropped: softmax-invariant)
__device__ __half g_wkh[Uq * Dq];      // Wk^T as half, [u][d] (B operand, K-contiguous)

// ---------------- helpers ----------------
__device__ __forceinline__ unsigned smem_u32(const void* p) {
    unsigned a;
    asm("{ .reg .u64 t; cvta.to.shared.u64 t, %1; cvt.u32.u64 %0, t; }" : "=r"(a) : "l"(p));
    return a;
}
__device__ __forceinline__ void cpasync16(unsigned dst, const void* src) {
    asm volatile("cp.async.cg.shared.global [%0], [%1], 16;" :: "r"(dst), "l"(src));
}
__device__ __forceinline__ unsigned h2tanh(unsigned x) {   // MUFU.TANH on 2 halves
    unsigned r;
    asm("tanh.approx.f16x2 %0, %1;" : "=r"(r) : "r"(x));
    return r;
}
__device__ __forceinline__ unsigned h2add(unsigned a, unsigned b) {
    unsigned r;
    asm("add.f16x2 %0, %1, %2;" : "=r"(r) : "r"(a), "r"(b));
    return r;
}
__device__ __forceinline__ void ldmx4(unsigned* r, unsigned addr) {
    asm volatile("ldmatrix.sync.aligned.m8n8.x4.shared.b16 {%0,%1,%2,%3}, [%4];"
                 : "=r"(r[0]), "=r"(r[1]), "=r"(r[2]), "=r"(r[3]) : "r"(addr));
}
// fp16-accumulate MMA: C/D are 2 regs of f16x2
__device__ __forceinline__ void mma_f16a(unsigned& c0, unsigned& c1, const unsigned* a,
                                         unsigned b0, unsigned b1) {
    asm volatile(
        "mma.sync.aligned.m16n8k16.row.col.f16.f16.f16.f16 "
        "{%0,%1}, {%2,%3,%4,%5}, {%6,%7}, {%0,%1};"
        : "+r"(c0), "+r"(c1)
        : "r"(a[0]), "r"(a[1]), "r"(a[2]), "r"(a[3]), "r"(b0), "r"(b1));
}

// ---------------------------------------------------------------------------
// Kernel 0 (prep, latency-parallelized):
//  blocks [0,256): uh partials. b = bx>>3, ks = bx&7; k in [ks*64, ks*64+64).
//    Each thread covers u = tid and tid+256. Bias folded into slice ks==0.
//    ks==7 blocks also zero the ctx slice for this replay.
//  blocks [256,512): g_wkh transpose tiles (32x32) + f32->f16.
// ---------------------------------------------------------------------------
__global__ __launch_bounds__(256)
void prep_kernel(const float* __restrict__ hidden,
                 const float* __restrict__ Uk,
                 const float* __restrict__ Ub,
                 const float* __restrict__ Wb,
                 const float* __restrict__ Wk,
                 float* __restrict__ ctx) {
    __shared__ float t[32][33];
    const int bx = blockIdx.x;
    const int tid = threadIdx.x;
    if (bx < 256) {
        const int b  = bx >> 3;
        const int ks = bx & 7;
        const int u0 = tid, u1 = tid + 256;
        if (ks == 7) {                           // zero context (any one slice works)
            ctx[b * Dq + u0] = 0.f;
            ctx[b * Dq + u1] = 0.f;
        }
        float a0 = (ks == 0) ? (Ub[u0] + Wb[u0]) : 0.f;
        float a1 = (ks == 0) ? (Ub[u1] + Wb[u1]) : 0.f;
        const float* h = hidden + b * 512;
        const int k0 = ks * 64;
        #pragma unroll 8
        for (int k = k0; k < k0 + 64; k++) {
            float hv = h[k];
            a0 = fmaf(hv, Uk[k * Uq + u0], a0);
            a1 = fmaf(hv, Uk[k * Uq + u1], a1);
        }
        g_uhp[(ks * Bq + b) * Uq + u0] = a0;
        g_uhp[(ks * Bq + b) * Uq + u1] = a1;
    } else {
        const int tt = bx - 256;                 // 0..255
        const int bu = (tt & 15) * 32, bd = (tt >> 4) * 32;
        const int tx = tid & 31, ty = tid >> 5;  // 32 x 8
        #pragma unroll
        for (int i = 0; i < 32; i += 8)
            t[ty + i][tx] = Wk[(bd + ty + i) * Uq + bu + tx];   // t[d][u]
        __syncthreads();
        #pragma unroll
        for (int i = 0; i < 32; i += 8)
            g_wkh[(bu + ty + i) * Dq + bd + tx] = __float2half(t[tx][ty + i]);
    }
}

// ---------------------------------------------------------------------------
// Kernel 1 (hot): R10/R12 winner. fp16-acc mma.sync m16n8k16 + ldmatrix.
// CTA: BM=64 x N=512, 8 warps (warp = m64 x n64), f16 acc (64 regs), occ 2.
// Only change vs R12: uh init sums the 8 k-split partials.
// ---------------------------------------------------------------------------
#define BM 64
#define KS 32
#define NSTG (Dq / KS)          // 16 stages, 2 k16-steps each
#define ROWB 80                 // padded row pitch in bytes (40 halves)
#define ABUF (BM * ROWB)        // 5120
#define BBUF (Uq * ROWB)        // 40960

#define SM_A    0                       // 2 x ABUF = 10240
#define SM_B    10240                   // 2 x BBUF = 81920
#define SM_UH   (SM_B + 2 * BBUF)       // 92160  (256 half2 = 1KB used)
#define SM_VK   (SM_UH + 2048)          // 94208  (512 floats)
#define SM_RED  (SM_VK + 2048)          // 96256  (64 floats)
#define SM_TOT  (SM_RED + 256)          // 96512 bytes -> 2 CTAs/SM

__global__ __launch_bounds__(256, 2)
void logits_kernel(const float* __restrict__ features,
                   const float* __restrict__ Vk) {
    extern __shared__ char smem[];
    const unsigned sb = smem_u32(smem);
    const int tid = threadIdx.x, lane = tid & 31, wid = tid >> 5;
    const int n0w = wid * 64;                   // warp's N offset
    const long row0 = (long)blockIdx.x * BM;
    const int b = (int)(row0 >> 11);

    unsigned* uh2s = (unsigned*)(smem + SM_UH);     // 256 x half2
    float*    vks  = (float*)(smem + SM_VK);
    float*    red  = (float*)(smem + SM_RED);

    {
        float s0 = 0.f, s1 = 0.f;
        #pragma unroll
        for (int j = 0; j < 8; j++) {
            float2 p = reinterpret_cast<const float2*>(g_uhp)[(j * Bq + b) * 256 + tid];
            s0 += p.x; s1 += p.y;
        }
        __half2 h = __floats2half2_rn(s0, s1);
        uh2s[tid] = *reinterpret_cast<unsigned*>(&h);
        vks[tid] = Vk[tid];
        vks[tid + 256] = Vk[tid + 256];
    }
    if (tid < BM) red[tid] = 0.f;

    const int ar_r   = tid >> 2;                // A row 0..63
    const int ar_k4a = (tid & 3) * 2;           // two consecutive float4 slots
    const int lr = lane & 7, sect = lane >> 3;  // ldmatrix lane addressing

    unsigned acc16[4][8][2];                    // f16x2 accumulators (64 regs)
    #pragma unroll
    for (int mi = 0; mi < 4; mi++)
        #pragma unroll
        for (int nt = 0; nt < 8; nt++) { acc16[mi][nt][0] = 0u; acc16[mi][nt][1] = 0u; }

    float4 ar[2][2];    // A global->reg double buffer

    auto loadA = [&](int s, int pb) {
        #pragma unroll
        for (int i = 0; i < 2; i++)
            ar[pb][i] = *reinterpret_cast<const float4*>(
                features + (row0 + ar_r) * Dq + s * KS + (ar_k4a + i) * 4);
    };
    auto storeA = [&](int buf, int pb) {
        #pragma unroll
        for (int i = 0; i < 2; i++) {
            float4 v = ar[pb][i];
            __half2 h0 = __floats2half2_rn(v.x, v.y);
            __half2 h1 = __floats2half2_rn(v.z, v.w);
            uint2 u = make_uint2(*reinterpret_cast<unsigned*>(&h0),
                                 *reinterpret_cast<unsigned*>(&h1));
            *reinterpret_cast<uint2*>(smem + SM_A + buf * ABUF +
                                      ar_r * ROWB + (ar_k4a + i) * 8) = u;
        }
    };
    auto fillB = [&](int s, int buf) {
        const unsigned bb = sb + SM_B + buf * BBUF;
        #pragma unroll
        for (int i = 0; i < 8; i++) {
            int idx = tid + i * 256;            // 0..2047
            int n = idx >> 2, c = idx & 3;
            cpasync16(bb + (unsigned)(n * ROWB + c * 16),
                      g_wkh + n * Dq + s * KS + c * 8);
        }
    };

    loadA(0, 0);
    fillB(0, 0);
    asm volatile("cp.async.commit_group;");

    for (int s = 0; s < NSTG; s++) {
        const int buf = s & 1;
        if (s + 1 < NSTG) {
            fillB(s + 1, 1 - buf);
            asm volatile("cp.async.commit_group;");
            loadA(s + 1, 1 - buf);
        }
        storeA(buf, buf);
        if (s + 1 < NSTG) asm volatile("cp.async.wait_group 1;");
        else              asm volatile("cp.async.wait_group 0;");
        __syncthreads();

        const unsigned ab = sb + SM_A + buf * ABUF;
        const unsigned bb = sb + SM_B + buf * BBUF;
        #pragma unroll
        for (int k16 = 0; k16 < 2; k16++) {
            const int kb = k16 * 16;            // halves offset within stage row
            unsigned af[4][4], bf[4][4];
            // A frags: (m0:8,k0:8),(m8:16,k0:8),(m0:8,k8:16),(m8:16,k8:16)
            #pragma unroll
            for (int mi = 0; mi < 4; mi++)
                ldmx4(af[mi], ab + (unsigned)((mi * 16 + (sect & 1) * 8 + lr) * ROWB
                                              + (kb + (sect >> 1) * 8) * 2));
            // B frags: (n0:8,k0:8),(n0:8,k8:16),(n8:16,k0:8),(n8:16,k8:16)
            #pragma unroll
            for (int nj = 0; nj < 4; nj++)
                ldmx4(bf[nj], bb + (unsigned)((n0w + nj * 16 + (sect >> 1) * 8 + lr) * ROWB
                                              + (kb + (sect & 1) * 8) * 2));
            #pragma unroll
            for (int mi = 0; mi < 4; mi++)
                #pragma unroll
                for (int nj = 0; nj < 4; nj++) {
                    mma_f16a(acc16[mi][2 * nj][0],     acc16[mi][2 * nj][1],
                             af[mi], bf[nj][0], bf[nj][1]);
                    mma_f16a(acc16[mi][2 * nj + 1][0], acc16[mi][2 * nj + 1][1],
                             af[mi], bf[nj][2], bf[nj][3]);
                }
        }
        __syncthreads();
    }

    // ---- epilogue: x = acc + uh (f16x2); tanh (f16x2); rowsum += Vk * tanh ----
    const int g = lane >> 2, t = lane & 3;
    float rs[8];
    #pragma unroll
    for (int i = 0; i < 8; i++) rs[i] = 0.f;
    #pragma unroll
    for (int mi = 0; mi < 4; mi++)
        #pragma unroll
        for (int nt = 0; nt < 8; nt++) {
            const int n = n0w + nt * 8 + 2 * t;
            unsigned uh2 = uh2s[n >> 1];
            float vk0 = vks[n], vk1 = vks[n + 1];
            unsigned t0 = h2tanh(h2add(acc16[mi][nt][0], uh2));
            float2 f0 = __half22float2(*reinterpret_cast<__half2*>(&t0));
            rs[mi * 2]     = fmaf(vk0, f0.x, fmaf(vk1, f0.y, rs[mi * 2]));
            unsigned t1 = h2tanh(h2add(acc16[mi][nt][1], uh2));
            float2 f1 = __half22float2(*reinterpret_cast<__half2*>(&t1));
            rs[mi * 2 + 1] = fmaf(vk0, f1.x, fmaf(vk1, f1.y, rs[mi * 2 + 1]));
        }
    #pragma unroll
    for (int i = 0; i < 8; i++) {
        rs[i] += __shfl_xor_sync(0xffffffffu, rs[i], 1);
        rs[i] += __shfl_xor_sync(0xffffffffu, rs[i], 2);
    }
    if (t == 0) {
        #pragma unroll
        for (int mi = 0; mi < 4; mi++) {
            atomicAdd(&red[mi * 16 + g],     rs[mi * 2]);
            atomicAdd(&red[mi * 16 + 8 + g], rs[mi * 2 + 1]);
        }
    }
    __syncthreads();
    if (tid < BM) g_logits[row0 + tid] = red[tid];
}

// ---------------------------------------------------------------------------
// Kernel 2 (fused softmax + context): each block recomputes row softmax stats
// from g_logits, writes its 128 weights to d_out, accumulates context partial.
// ---------------------------------------------------------------------------
#define TCHUNK 128
__global__ __launch_bounds__(256, 8)
void ctxw_kernel(const float* __restrict__ features,
                 float* __restrict__ out_w,
                 float* __restrict__ ctx) {
    __shared__ float sm[256];
    __shared__ float ws[TCHUNK];
    const int b  = blockIdx.y;
    const int t0 = blockIdx.x * TCHUNK;
    const int tid = threadIdx.x;
    const float* lg = g_logits + b * Tq;

    float lv[8];
    float mx = -1e30f;
    #pragma unroll
    for (int i = 0; i < 8; i++) { lv[i] = lg[tid + i * 256]; mx = fmaxf(mx, lv[i]); }
    sm[tid] = mx; __syncthreads();
    for (int s = 128; s > 0; s >>= 1) {
        if (tid < s) sm[tid] = fmaxf(sm[tid], sm[tid + s]);
        __syncthreads();
    }
    mx = sm[0]; __syncthreads();
    float sum = 0.f;
    #pragma unroll
    for (int i = 0; i < 8; i++) sum += expf(lv[i] - mx);
    sm[tid] = sum; __syncthreads();
    for (int s = 128; s > 0; s >>= 1) {
        if (tid < s) sm[tid] += sm[tid + s];
        __syncthreads();
    }
    const float inv = 1.f / sm[0];

    if (tid < TCHUNK) {
        float w = expf(lg[t0 + tid] - mx) * inv;
        ws[tid] = w;
        out_w[b * Tq + t0 + tid] = w;
    }
    __syncthreads();

    const int d4 = tid & 127;
    const int tp = tid >> 7;
    const float* fb = features + (long)b * Tq * Dq + (long)t0 * Dq + d4 * 4;
    float4 acc = make_float4(0.f, 0.f, 0.f, 0.f);
    #pragma unroll 8
    for (int i = tp; i < TCHUNK; i += 2) {
        float  wt = ws[i];
        float4 v  = *reinterpret_cast<const float4*>(fb + (long)i * Dq);
        acc.x = fmaf(wt, v.x, acc.x);
        acc.y = fmaf(wt, v.y, acc.y);
        acc.z = fmaf(wt, v.z, acc.z);
        acc.w = fmaf(wt, v.w, acc.w);
    }
    float* dst = ctx + b * Dq + d4 * 4;
    atomicAdd(dst + 0, acc.x);
    atomicAdd(dst + 1, acc.y);
    atomicAdd(dst + 2, acc.z);
    atomicAdd(dst + 3, acc.w);
}

// ---------------------------------------------------------------------------
extern "C" void kernel_launch(void* const* d_in, const int* in_sizes, int n_in,
                              void* d_out, int out_size) {
    const float* features = (const float*)d_in[0];  // [B,T,D]
    const float* hidden   = (const float*)d_in[1];  // [B,H]
    const float* Wk       = (const float*)d_in[2];  // [D,U]
    const float* Wb       = (const float*)d_in[3];  // [U]
    const float* Uk       = (const float*)d_in[4];  // [H,U]
    const float* Ub       = (const float*)d_in[5];  // [U]
    const float* Vk       = (const float*)d_in[6];  // [U,1]
    // d_in[7] = Vb [1]: uniform logit shift -> softmax-invariant -> unused.

    float* out  = (float*)d_out;
    float* ctx  = out;               // context_vector [B, D]  (tuple output 0)
    float* attw = out + Bq * Dq;     // attention_weights [B, T, 1] (tuple output 1)

    cudaFuncSetAttribute(logits_kernel,
                         cudaFuncAttributeMaxDynamicSharedMemorySize, SM_TOT);

    prep_kernel<<<512, 256>>>(hidden, Uk, Ub, Wb, Wk, ctx);
    logits_kernel<<<(Bq * Tq) / BM, 256, SM_TOT>>>(features, Vk);
    ctxw_kernel<<<dim3(Tq / TCHUNK, Bq), 256>>>(features, attw, ctx);
}

// round 14
// speedup vs baseline: 1.3182x; 1.0122x over previous
#include <cuda_runtime.h>
#include <cuda_fp16.h>
#include <math.h>

// Problem dims (fixed by the reference)
#define Bq 32
#define Tq 2048
#define Dq 512
#define Uq 512

// Scratch (no device allocation allowed -> __device__ globals)
#define UHS 16                           // uh k-split factor
__device__ float  g_uhp[UHS * Bq * Uq];  // k-split partials of hidden@Uk (+bias slice 0)
__device__ float  g_logits[Bq * Tq];     // pre-softmax logits (Vb dropped: softmax-invariant)
__device__ float  g_smax[Bq];            // per-batch logit max
__device__ float  g_sinv[Bq];            // per-batch 1/sum(exp)
__device__ __half g_wkh[Uq * Dq];        // Wk^T as half, [u][d] (B operand, K-contiguous)

// ---------------- helpers ----------------
__device__ __forceinline__ unsigned smem_u32(const void* p) {
    unsigned a;
    asm("{ .reg .u64 t; cvta.to.shared.u64 t, %1; cvt.u32.u64 %0, t; }" : "=r"(a) : "l"(p));
    return a;
}
__device__ __forceinline__ void cpasync16(unsigned dst, const void* src) {
    asm volatile("cp.async.cg.shared.global [%0], [%1], 16;" :: "r"(dst), "l"(src));
}
__device__ __forceinline__ unsigned h2tanh(unsigned x) {   // MUFU.TANH on 2 halves
    unsigned r;
    asm("tanh.approx.f16x2 %0, %1;" : "=r"(r) : "r"(x));
    return r;
}
__device__ __forceinline__ unsigned h2add(unsigned a, unsigned b) {
    unsigned r;
    asm("add.f16x2 %0, %1, %2;" : "=r"(r) : "r"(a), "r"(b));
    return r;
}
__device__ __forceinline__ void ldmx4(unsigned* r, unsigned addr) {
    asm volatile("ldmatrix.sync.aligned.m8n8.x4.shared.b16 {%0,%1,%2,%3}, [%4];"
                 : "=r"(r[0]), "=r"(r[1]), "=r"(r[2]), "=r"(r[3]) : "r"(addr));
}
// fp16-accumulate MMA: C/D are 2 regs of f16x2
__device__ __forceinline__ void mma_f16a(unsigned& c0, unsigned& c1, const unsigned* a,
                                         unsigned b0, unsigned b1) {
    asm volatile(
        "mma.sync.aligned.m16n8k16.row.col.f16.f16.f16.f16 "
        "{%0,%1}, {%2,%3,%4,%5}, {%6,%7}, {%0,%1};"
        : "+r"(c0), "+r"(c1)
        : "r"(a[0]), "r"(a[1]), "r"(a[2]), "r"(a[3]), "r"(b0), "r"(b1));
}

// ---------------------------------------------------------------------------
// Kernel 0 (prep, latency-parallelized):
//  blocks [0,512): uh partials. b = bx>>4, ks = bx&15; k in [ks*32, ks*32+32).
//    Each thread covers u = tid and tid+256. Bias in slice 0; ctx zero in slice 15.
//  blocks [512,768): g_wkh transpose tiles (32x32) + f32->f16.
// ---------------------------------------------------------------------------
__global__ __launch_bounds__(256)
void prep_kernel(const float* __restrict__ hidden,
                 const float* __restrict__ Uk,
                 const float* __restrict__ Ub,
                 const float* __restrict__ Wb,
                 const float* __restrict__ Wk,
                 float* __restrict__ ctx) {
    __shared__ float t[32][33];
    const int bx = blockIdx.x;
    const int tid = threadIdx.x;
    if (bx < 512) {
        const int b  = bx >> 4;
        const int ks = bx & 15;
        const int u0 = tid, u1 = tid + 256;
        if (ks == 15) {                          // zero context (one slice only)
            ctx[b * Dq + u0] = 0.f;
            ctx[b * Dq + u1] = 0.f;
        }
        float a0 = (ks == 0) ? (Ub[u0] + Wb[u0]) : 0.f;
        float a1 = (ks == 0) ? (Ub[u1] + Wb[u1]) : 0.f;
        const float* h = hidden + b * 512;
        const int k0 = ks * 32;
        #pragma unroll 8
        for (int k = k0; k < k0 + 32; k++) {
            float hv = h[k];
            a0 = fmaf(hv, Uk[k * Uq + u0], a0);
            a1 = fmaf(hv, Uk[k * Uq + u1], a1);
        }
        g_uhp[(ks * Bq + b) * Uq + u0] = a0;
        g_uhp[(ks * Bq + b) * Uq + u1] = a1;
    } else {
        const int tt = bx - 512;                 // 0..255
        const int bu = (tt & 15) * 32, bd = (tt >> 4) * 32;
        const int tx = tid & 31, ty = tid >> 5;  // 32 x 8
        #pragma unroll
        for (int i = 0; i < 32; i += 8)
            t[ty + i][tx] = Wk[(bd + ty + i) * Uq + bu + tx];   // t[d][u]
        __syncthreads();
        #pragma unroll
        for (int i = 0; i < 32; i += 8)
            g_wkh[(bu + ty + i) * Dq + bd + tx] = __float2half(t[tx][ty + i]);
    }
}

// ---------------------------------------------------------------------------
// Kernel 1 (hot): R10/R12 winner verbatim (BM=64 x N=512, 8 warps, f16 acc,
// occ 2). uh init sums the 16 k-split partials.
// ---------------------------------------------------------------------------
#define BM 64
#define KS 32
#define NSTG (Dq / KS)          // 16 stages, 2 k16-steps each
#define ROWB 80                 // padded row pitch in bytes (40 halves)
#define ABUF (BM * ROWB)        // 5120
#define BBUF (Uq * ROWB)        // 40960

#define SM_A    0                       // 2 x ABUF = 10240
#define SM_B    10240                   // 2 x BBUF = 81920
#define SM_UH   (SM_B + 2 * BBUF)       // 92160  (256 half2 = 1KB used)
#define SM_VK   (SM_UH + 2048)          // 94208  (512 floats)
#define SM_RED  (SM_VK + 2048)          // 96256  (64 floats)
#define SM_TOT  (SM_RED + 256)          // 96512 bytes -> 2 CTAs/SM

__global__ __launch_bounds__(256, 2)
void logits_kernel(const float* __restrict__ features,
                   const float* __restrict__ Vk) {
    extern __shared__ char smem[];
    const unsigned sb = smem_u32(smem);
    const int tid = threadIdx.x, lane = tid & 31, wid = tid >> 5;
    const int n0w = wid * 64;                   // warp's N offset
    const long row0 = (long)blockIdx.x * BM;
    const int b = (int)(row0 >> 11);

    unsigned* uh2s = (unsigned*)(smem + SM_UH);     // 256 x half2
    float*    vks  = (float*)(smem + SM_VK);
    float*    red  = (float*)(smem + SM_RED);

    {
        float s0 = 0.f, s1 = 0.f;
        #pragma unroll
        for (int j = 0; j < UHS; j++) {
            float2 p = reinterpret_cast<const float2*>(g_uhp)[(j * Bq + b) * 256 + tid];
            s0 += p.x; s1 += p.y;
        }
        __half2 h = __floats2half2_rn(s0, s1);
        uh2s[tid] = *reinterpret_cast<unsigned*>(&h);
        vks[tid] = Vk[tid];
        vks[tid + 256] = Vk[tid + 256];
    }
    if (tid < BM) red[tid] = 0.f;

    const int ar_r   = tid >> 2;                // A row 0..63
    const int ar_k4a = (tid & 3) * 2;           // two consecutive float4 slots
    const int lr = lane & 7, sect = lane >> 3;  // ldmatrix lane addressing

    unsigned acc16[4][8][2];                    // f16x2 accumulators (64 regs)
    #pragma unroll
    for (int mi = 0; mi < 4; mi++)
        #pragma unroll
        for (int nt = 0; nt < 8; nt++) { acc16[mi][nt][0] = 0u; acc16[mi][nt][1] = 0u; }

    float4 ar[2][2];    // A global->reg double buffer

    auto loadA = [&](int s, int pb) {
        #pragma unroll
        for (int i = 0; i < 2; i++)
            ar[pb][i] = *reinterpret_cast<const float4*>(
                features + (row0 + ar_r) * Dq + s * KS + (ar_k4a + i) * 4);
    };
    auto storeA = [&](int buf, int pb) {
        #pragma unroll
        for (int i = 0; i < 2; i++) {
            float4 v = ar[pb][i];
            __half2 h0 = __floats2half2_rn(v.x, v.y);
            __half2 h1 = __floats2half2_rn(v.z, v.w);
            uint2 u = make_uint2(*reinterpret_cast<unsigned*>(&h0),
                                 *reinterpret_cast<unsigned*>(&h1));
            *reinterpret_cast<uint2*>(smem + SM_A + buf * ABUF +
                                      ar_r * ROWB + (ar_k4a + i) * 8) = u;
        }
    };
    auto fillB = [&](int s, int buf) {
        const unsigned bb = sb + SM_B + buf * BBUF;
        #pragma unroll
        for (int i = 0; i < 8; i++) {
            int idx = tid + i * 256;            // 0..2047
            int n = idx >> 2, c = idx & 3;
            cpasync16(bb + (unsigned)(n * ROWB + c * 16),
                      g_wkh + n * Dq + s * KS + c * 8);
        }
    };

    loadA(0, 0);
    fillB(0, 0);
    asm volatile("cp.async.commit_group;");

    for (int s = 0; s < NSTG; s++) {
        const int buf = s & 1;
        if (s + 1 < NSTG) {
            fillB(s + 1, 1 - buf);
            asm volatile("cp.async.commit_group;");
            loadA(s + 1, 1 - buf);
        }
        storeA(buf, buf);
        if (s + 1 < NSTG) asm volatile("cp.async.wait_group 1;");
        else              asm volatile("cp.async.wait_group 0;");
        __syncthreads();

        const unsigned ab = sb + SM_A + buf * ABUF;
        const unsigned bb = sb + SM_B + buf * BBUF;
        #pragma unroll
        for (int k16 = 0; k16 < 2; k16++) {
            const int kb = k16 * 16;            // halves offset within stage row
            unsigned af[4][4], bf[4][4];
            // A frags: (m0:8,k0:8),(m8:16,k0:8),(m0:8,k8:16),(m8:16,k8:16)
            #pragma unroll
            for (int mi = 0; mi < 4; mi++)
                ldmx4(af[mi], ab + (unsigned)((mi * 16 + (sect & 1) * 8 + lr) * ROWB
                                              + (kb + (sect >> 1) * 8) * 2));
            // B frags: (n0:8,k0:8),(n0:8,k8:16),(n8:16,k0:8),(n8:16,k8:16)
            #pragma unroll
            for (int nj = 0; nj < 4; nj++)
                ldmx4(bf[nj], bb + (unsigned)((n0w + nj * 16 + (sect >> 1) * 8 + lr) * ROWB
                                              + (kb + (sect & 1) * 8) * 2));
            #pragma unroll
            for (int mi = 0; mi < 4; mi++)
                #pragma unroll
                for (int nj = 0; nj < 4; nj++) {
                    mma_f16a(acc16[mi][2 * nj][0],     acc16[mi][2 * nj][1],
                             af[mi], bf[nj][0], bf[nj][1]);
                    mma_f16a(acc16[mi][2 * nj + 1][0], acc16[mi][2 * nj + 1][1],
                             af[mi], bf[nj][2], bf[nj][3]);
                }
        }
        __syncthreads();
    }

    // ---- epilogue: x = acc + uh (f16x2); tanh (f16x2); rowsum += Vk * tanh ----
    const int g = lane >> 2, t = lane & 3;
    float rs[8];
    #pragma unroll
    for (int i = 0; i < 8; i++) rs[i] = 0.f;
    #pragma unroll
    for (int mi = 0; mi < 4; mi++)
        #pragma unroll
        for (int nt = 0; nt < 8; nt++) {
            const int n = n0w + nt * 8 + 2 * t;
            unsigned uh2 = uh2s[n >> 1];
            float vk0 = vks[n], vk1 = vks[n + 1];
            unsigned t0 = h2tanh(h2add(acc16[mi][nt][0], uh2));
            float2 f0 = __half22float2(*reinterpret_cast<__half2*>(&t0));
            rs[mi * 2]     = fmaf(vk0, f0.x, fmaf(vk1, f0.y, rs[mi * 2]));
            unsigned t1 = h2tanh(h2add(acc16[mi][nt][1], uh2));
            float2 f1 = __half22float2(*reinterpret_cast<__half2*>(&t1));
            rs[mi * 2 + 1] = fmaf(vk0, f1.x, fmaf(vk1, f1.y, rs[mi * 2 + 1]));
        }
    #pragma unroll
    for (int i = 0; i < 8; i++) {
        rs[i] += __shfl_xor_sync(0xffffffffu, rs[i], 1);
        rs[i] += __shfl_xor_sync(0xffffffffu, rs[i], 2);
    }
    if (t == 0) {
        #pragma unroll
        for (int mi = 0; mi < 4; mi++) {
            atomicAdd(&red[mi * 16 + g],     rs[mi * 2]);
            atomicAdd(&red[mi * 16 + 8 + g], rs[mi * 2 + 1]);
        }
    }
    __syncthreads();
    if (tid < BM) g_logits[row0 + tid] = red[tid];
}

// ---------------------------------------------------------------------------
// Kernel 2 (softmax stats): per-batch max and 1/sum(exp). 32 blocks.
// ---------------------------------------------------------------------------
__global__ __launch_bounds__(256)
void stats_kernel() {
    const int b = blockIdx.x;
    const int tid = threadIdx.x;
    __shared__ float sm[256];
    const float* lg = g_logits + b * Tq;

    float lv[8];
    float mx = -1e30f;
    #pragma unroll
    for (int i = 0; i < 8; i++) { lv[i] = lg[tid + i * 256]; mx = fmaxf(mx, lv[i]); }
    sm[tid] = mx; __syncthreads();
    for (int s = 128; s > 0; s >>= 1) {
        if (tid < s) sm[tid] = fmaxf(sm[tid], sm[tid + s]);
        __syncthreads();
    }
    mx = sm[0]; __syncthreads();
    float sum = 0.f;
    #pragma unroll
    for (int i = 0; i < 8; i++) sum += expf(lv[i] - mx);
    sm[tid] = sum; __syncthreads();
    for (int s = 128; s > 0; s >>= 1) {
        if (tid < s) sm[tid] += sm[tid + s];
        __syncthreads();
    }
    if (tid == 0) { g_smax[b] = mx; g_sinv[b] = 1.f / sm[0]; }
}

// ---------------------------------------------------------------------------
// Kernel 3 (weights + context): stats precomputed -> stream immediately.
// ---------------------------------------------------------------------------
#define TCHUNK 128
__global__ __launch_bounds__(256, 8)
void ctxw_kernel(const float* __restrict__ features,
                 float* __restrict__ out_w,
                 float* __restrict__ ctx) {
    __shared__ float ws[TCHUNK];
    const int b  = blockIdx.y;
    const int t0 = blockIdx.x * TCHUNK;
    const int tid = threadIdx.x;

    const float mx  = g_smax[b];
    const float inv = g_sinv[b];
    if (tid < TCHUNK) {
        float w = expf(g_logits[b * Tq + t0 + tid] - mx) * inv;
        ws[tid] = w;
        out_w[b * Tq + t0 + tid] = w;
    }
    __syncthreads();

    const int d4 = tid & 127;
    const int tp = tid >> 7;
    const float* fb = features + (long)b * Tq * Dq + (long)t0 * Dq + d4 * 4;
    float4 acc = make_float4(0.f, 0.f, 0.f, 0.f);
    #pragma unroll 8
    for (int i = tp; i < TCHUNK; i += 2) {
        float  wt = ws[i];
        float4 v  = *reinterpret_cast<const float4*>(fb + (long)i * Dq);
        acc.x = fmaf(wt, v.x, acc.x);
        acc.y = fmaf(wt, v.y, acc.y);
        acc.z = fmaf(wt, v.z, acc.z);
        acc.w = fmaf(wt, v.w, acc.w);
    }
    float* dst = ctx + b * Dq + d4 * 4;
    atomicAdd(dst + 0, acc.x);
    atomicAdd(dst + 1, acc.y);
    atomicAdd(dst + 2, acc.z);
    atomicAdd(dst + 3, acc.w);
}

// ---------------------------------------------------------------------------
extern "C" void kernel_launch(void* const* d_in, const int* in_sizes, int n_in,
                              void* d_out, int out_size) {
    const float* features = (const float*)d_in[0];  // [B,T,D]
    const float* hidden   = (const float*)d_in[1];  // [B,H]
    const float* Wk       = (const float*)d_in[2];  // [D,U]
    const float* Wb       = (const float*)d_in[3];  // [U]
    const float* Uk       = (const float*)d_in[4];  // [H,U]
    const float* Ub       = (const float*)d_in[5];  // [U]
    const float* Vk       = (const float*)d_in[6];  // [U,1]
    // d_in[7] = Vb [1]: uniform logit shift -> softmax-invariant -> unused.

    float* out  = (float*)d_out;
    float* ctx  = out;               // context_vector [B, D]  (tuple output 0)
    float* attw = out + Bq * Dq;     // attention_weights [B, T, 1] (tuple output 1)

    cudaFuncSetAttribute(logits_kernel,
                         cudaFuncAttributeMaxDynamicSharedMemorySize, SM_TOT);

    prep_kernel<<<768, 256>>>(hidden, Uk, Ub, Wb, Wk, ctx);
    logits_kernel<<<(Bq * Tq) / BM, 256, SM_TOT>>>(features, Vk);
    stats_kernel<<<Bq, 256>>>();
    ctxw_kernel<<<dim3(Tq / TCHUNK, Bq), 256>>>(features, attw, ctx);
}

// round 15
// speedup vs baseline: 1.3413x; 1.0175x over previous
#include <cuda_runtime.h>
#include <cuda_fp16.h>
#include <math.h>

// Problem dims (fixed by the reference)
#define Bq 32
#define Tq 2048
#define Dq 512
#define Uq 512

// Scratch (no device allocation allowed -> __device__ globals)
#define UHS 16                           // uh k-split factor
__device__ float  g_uhp[UHS * Bq * Uq];  // k-split partials of hidden@Uk (+bias slice 0)
__device__ float  g_logits[Bq * Tq];     // pre-softmax logits (Vb dropped: softmax-invariant)
__device__ float  g_smax[Bq];            // per-batch logit max
__device__ float  g_sinv[Bq];            // per-batch 1/sum(exp)
__device__ __half g_wkh[Uq * Dq];        // Wk^T as half, [u][d] (B operand, K-contiguous)

// ---------------- helpers ----------------
__device__ __forceinline__ unsigned smem_u32(const void* p) {
    unsigned a;
    asm("{ .reg .u64 t; cvta.to.shared.u64 t, %1; cvt.u32.u64 %0, t; }" : "=r"(a) : "l"(p));
    return a;
}
__device__ __forceinline__ void cpasync16(unsigned dst, const void* src) {
    asm volatile("cp.async.cg.shared.global [%0], [%1], 16;" :: "r"(dst), "l"(src));
}
__device__ __forceinline__ unsigned h2tanh(unsigned x) {   // MUFU.TANH on 2 halves
    unsigned r;
    asm("tanh.approx.f16x2 %0, %1;" : "=r"(r) : "r"(x));
    return r;
}
__device__ __forceinline__ unsigned h2add(unsigned a, unsigned b) {
    unsigned r;
    asm("add.f16x2 %0, %1, %2;" : "=r"(r) : "r"(a), "r"(b));
    return r;
}
__device__ __forceinline__ void ldmx4(unsigned* r, unsigned addr) {
    asm volatile("ldmatrix.sync.aligned.m8n8.x4.shared.b16 {%0,%1,%2,%3}, [%4];"
                 : "=r"(r[0]), "=r"(r[1]), "=r"(r[2]), "=r"(r[3]) : "r"(addr));
}
// fp16-accumulate MMA: C/D are 2 regs of f16x2
__device__ __forceinline__ void mma_f16a(unsigned& c0, unsigned& c1, const unsigned* a,
                                         unsigned b0, unsigned b1) {
    asm volatile(
        "mma.sync.aligned.m16n8k16.row.col.f16.f16.f16.f16 "
        "{%0,%1}, {%2,%3,%4,%5}, {%6,%7}, {%0,%1};"
        : "+r"(c0), "+r"(c1)
        : "r"(a[0]), "r"(a[1]), "r"(a[2]), "r"(a[3]), "r"(b0), "r"(b1));
}

// ---------------------------------------------------------------------------
// Kernel 0 (prep, latency-parallelized):
//  blocks [0,512): uh partials. b = bx>>4, ks = bx&15; k in [ks*32, ks*32+32).
//  blocks [512,768): g_wkh transpose tiles (32x32) + f32->f16.
// ---------------------------------------------------------------------------
__global__ __launch_bounds__(256)
void prep_kernel(const float* __restrict__ hidden,
                 const float* __restrict__ Uk,
                 const float* __restrict__ Ub,
                 const float* __restrict__ Wb,
                 const float* __restrict__ Wk,
                 float* __restrict__ ctx) {
    __shared__ float t[32][33];
    const int bx = blockIdx.x;
    const int tid = threadIdx.x;
    if (bx < 512) {
        const int b  = bx >> 4;
        const int ks = bx & 15;
        const int u0 = tid, u1 = tid + 256;
        if (ks == 15) {                          // zero context (one slice only)
            ctx[b * Dq + u0] = 0.f;
            ctx[b * Dq + u1] = 0.f;
        }
        float a0 = (ks == 0) ? (Ub[u0] + Wb[u0]) : 0.f;
        float a1 = (ks == 0) ? (Ub[u1] + Wb[u1]) : 0.f;
        const float* h = hidden + b * 512;
        const int k0 = ks * 32;
        #pragma unroll 8
        for (int k = k0; k < k0 + 32; k++) {
            float hv = h[k];
            a0 = fmaf(hv, Uk[k * Uq + u0], a0);
            a1 = fmaf(hv, Uk[k * Uq + u1], a1);
        }
        g_uhp[(ks * Bq + b) * Uq + u0] = a0;
        g_uhp[(ks * Bq + b) * Uq + u1] = a1;
    } else {
        const int tt = bx - 512;                 // 0..255
        const int bu = (tt & 15) * 32, bd = (tt >> 4) * 32;
        const int tx = tid & 31, ty = tid >> 5;  // 32 x 8
        #pragma unroll
        for (int i = 0; i < 32; i += 8)
            t[ty + i][tx] = Wk[(bd + ty + i) * Uq + bu + tx];   // t[d][u]
        __syncthreads();
        #pragma unroll
        for (int i = 0; i < 32; i += 8)
            g_wkh[(bu + ty + i) * Dq + bd + tx] = __float2half(t[tx][ty + i]);
    }
}

// ---------------------------------------------------------------------------
// Kernel 1 (hot): R10/R12 winner verbatim (BM=64 x N=512, 8 warps, f16 acc,
// occ 2). uh init sums the 16 k-split partials.
// ---------------------------------------------------------------------------
#define BM 64
#define KS 32
#define NSTG (Dq / KS)          // 16 stages, 2 k16-steps each
#define ROWB 80                 // padded row pitch in bytes (40 halves)
#define ABUF (BM * ROWB)        // 5120
#define BBUF (Uq * ROWB)        // 40960

#define SM_A    0                       // 2 x ABUF = 10240
#define SM_B    10240                   // 2 x BBUF = 81920
#define SM_UH   (SM_B + 2 * BBUF)       // 92160  (256 half2 = 1KB used)
#define SM_VK   (SM_UH + 2048)          // 94208  (512 floats)
#define SM_RED  (SM_VK + 2048)          // 96256  (64 floats)
#define SM_TOT  (SM_RED + 256)          // 96512 bytes -> 2 CTAs/SM

__global__ __launch_bounds__(256, 2)
void logits_kernel(const float* __restrict__ features,
                   const float* __restrict__ Vk) {
    extern __shared__ char smem[];
    const unsigned sb = smem_u32(smem);
    const int tid = threadIdx.x, lane = tid & 31, wid = tid >> 5;
    const int n0w = wid * 64;                   // warp's N offset
    const long row0 = (long)blockIdx.x * BM;
    const int b = (int)(row0 >> 11);

    unsigned* uh2s = (unsigned*)(smem + SM_UH);     // 256 x half2
    float*    vks  = (float*)(smem + SM_VK);
    float*    red  = (float*)(smem + SM_RED);

    {
        float s0 = 0.f, s1 = 0.f;
        #pragma unroll
        for (int j = 0; j < UHS; j++) {
            float2 p = reinterpret_cast<const float2*>(g_uhp)[(j * Bq + b) * 256 + tid];
            s0 += p.x; s1 += p.y;
        }
        __half2 h = __floats2half2_rn(s0, s1);
        uh2s[tid] = *reinterpret_cast<unsigned*>(&h);
        vks[tid] = Vk[tid];
        vks[tid + 256] = Vk[tid + 256];
    }
    if (tid < BM) red[tid] = 0.f;

    const int ar_r   = tid >> 2;                // A row 0..63
    const int ar_k4a = (tid & 3) * 2;           // two consecutive float4 slots
    const int lr = lane & 7, sect = lane >> 3;  // ldmatrix lane addressing

    unsigned acc16[4][8][2];                    // f16x2 accumulators (64 regs)
    #pragma unroll
    for (int mi = 0; mi < 4; mi++)
        #pragma unroll
        for (int nt = 0; nt < 8; nt++) { acc16[mi][nt][0] = 0u; acc16[mi][nt][1] = 0u; }

    float4 ar[2][2];    // A global->reg double buffer

    auto loadA = [&](int s, int pb) {
        #pragma unroll
        for (int i = 0; i < 2; i++)
            ar[pb][i] = *reinterpret_cast<const float4*>(
                features + (row0 + ar_r) * Dq + s * KS + (ar_k4a + i) * 4);
    };
    auto storeA = [&](int buf, int pb) {
        #pragma unroll
        for (int i = 0; i < 2; i++) {
            float4 v = ar[pb][i];
            __half2 h0 = __floats2half2_rn(v.x, v.y);
            __half2 h1 = __floats2half2_rn(v.z, v.w);
            uint2 u = make_uint2(*reinterpret_cast<unsigned*>(&h0),
                                 *reinterpret_cast<unsigned*>(&h1));
            *reinterpret_cast<uint2*>(smem + SM_A + buf * ABUF +
                                      ar_r * ROWB + (ar_k4a + i) * 8) = u;
        }
    };
    auto fillB = [&](int s, int buf) {
        const unsigned bb = sb + SM_B + buf * BBUF;
        #pragma unroll
        for (int i = 0; i < 8; i++) {
            int idx = tid + i * 256;            // 0..2047
            int n = idx >> 2, c = idx & 3;
            cpasync16(bb + (unsigned)(n * ROWB + c * 16),
                      g_wkh + n * Dq + s * KS + c * 8);
        }
    };

    loadA(0, 0);
    fillB(0, 0);
    asm volatile("cp.async.commit_group;");

    for (int s = 0; s < NSTG; s++) {
        const int buf = s & 1;
        if (s + 1 < NSTG) {
            fillB(s + 1, 1 - buf);
            asm volatile("cp.async.commit_group;");
            loadA(s + 1, 1 - buf);
        }
        storeA(buf, buf);
        if (s + 1 < NSTG) asm volatile("cp.async.wait_group 1;");
        else              asm volatile("cp.async.wait_group 0;");
        __syncthreads();

        const unsigned ab = sb + SM_A + buf * ABUF;
        const unsigned bb = sb + SM_B + buf * BBUF;
        #pragma unroll
        for (int k16 = 0; k16 < 2; k16++) {
            const int kb = k16 * 16;            // halves offset within stage row
            unsigned af[4][4], bf[4][4];
            // A frags: (m0:8,k0:8),(m8:16,k0:8),(m0:8,k8:16),(m8:16,k8:16)
            #pragma unroll
            for (int mi = 0; mi < 4; mi++)
                ldmx4(af[mi], ab + (unsigned)((mi * 16 + (sect & 1) * 8 + lr) * ROWB
                                              + (kb + (sect >> 1) * 8) * 2));
            // B frags: (n0:8,k0:8),(n0:8,k8:16),(n8:16,k0:8),(n8:16,k8:16)
            #pragma unroll
            for (int nj = 0; nj < 4; nj++)
                ldmx4(bf[nj], bb + (unsigned)((n0w + nj * 16 + (sect >> 1) * 8 + lr) * ROWB
                                              + (kb + (sect & 1) * 8) * 2));
            #pragma unroll
            for (int mi = 0; mi < 4; mi++)
                #pragma unroll
                for (int nj = 0; nj < 4; nj++) {
                    mma_f16a(acc16[mi][2 * nj][0],     acc16[mi][2 * nj][1],
                             af[mi], bf[nj][0], bf[nj][1]);
                    mma_f16a(acc16[mi][2 * nj + 1][0], acc16[mi][2 * nj + 1][1],
                             af[mi], bf[nj][2], bf[nj][3]);
                }
        }
        __syncthreads();
    }

    // ---- epilogue: x = acc + uh (f16x2); tanh (f16x2); rowsum += Vk * tanh ----
    const int g = lane >> 2, t = lane & 3;
    float rs[8];
    #pragma unroll
    for (int i = 0; i < 8; i++) rs[i] = 0.f;
    #pragma unroll
    for (int mi = 0; mi < 4; mi++)
        #pragma unroll
        for (int nt = 0; nt < 8; nt++) {
            const int n = n0w + nt * 8 + 2 * t;
            unsigned uh2 = uh2s[n >> 1];
            float vk0 = vks[n], vk1 = vks[n + 1];
            unsigned t0 = h2tanh(h2add(acc16[mi][nt][0], uh2));
            float2 f0 = __half22float2(*reinterpret_cast<__half2*>(&t0));
            rs[mi * 2]     = fmaf(vk0, f0.x, fmaf(vk1, f0.y, rs[mi * 2]));
            unsigned t1 = h2tanh(h2add(acc16[mi][nt][1], uh2));
            float2 f1 = __half22float2(*reinterpret_cast<__half2*>(&t1));
            rs[mi * 2 + 1] = fmaf(vk0, f1.x, fmaf(vk1, f1.y, rs[mi * 2 + 1]));
        }
    #pragma unroll
    for (int i = 0; i < 8; i++) {
        rs[i] += __shfl_xor_sync(0xffffffffu, rs[i], 1);
        rs[i] += __shfl_xor_sync(0xffffffffu, rs[i], 2);
    }
    if (t == 0) {
        #pragma unroll
        for (int mi = 0; mi < 4; mi++) {
            atomicAdd(&red[mi * 16 + g],     rs[mi * 2]);
            atomicAdd(&red[mi * 16 + 8 + g], rs[mi * 2 + 1]);
        }
    }
    __syncthreads();
    if (tid < BM) g_logits[row0 + tid] = red[tid];
}

// ---------------------------------------------------------------------------
// Kernel 2 (softmax stats): per-batch max and 1/sum(exp). 32 blocks.
// ---------------------------------------------------------------------------
__global__ __launch_bounds__(256)
void stats_kernel() {
    const int b = blockIdx.x;
    const int tid = threadIdx.x;
    __shared__ float sm[256];
    const float* lg = g_logits + b * Tq;

    float lv[8];
    float mx = -1e30f;
    #pragma unroll
    for (int i = 0; i < 8; i++) { lv[i] = lg[tid + i * 256]; mx = fmaxf(mx, lv[i]); }
    sm[tid] = mx; __syncthreads();
    for (int s = 128; s > 0; s >>= 1) {
        if (tid < s) sm[tid] = fmaxf(sm[tid], sm[tid + s]);
        __syncthreads();
    }
    mx = sm[0]; __syncthreads();
    float sum = 0.f;
    #pragma unroll
    for (int i = 0; i < 8; i++) sum += expf(lv[i] - mx);
    sm[tid] = sum; __syncthreads();
    for (int s = 128; s > 0; s >>= 1) {
        if (tid < s) sm[tid] += sm[tid + s];
        __syncthreads();
    }
    if (tid == 0) { g_smax[b] = mx; g_sinv[b] = 1.f / sm[0]; }
}

// ---------------------------------------------------------------------------
// Kernel 3 (weights + context): TCHUNK=64 -> 1024 blocks for occupancy/MLP.
// ---------------------------------------------------------------------------
#define TCHUNK 64
__global__ __launch_bounds__(256, 8)
void ctxw_kernel(const float* __restrict__ features,
                 float* __restrict__ out_w,
                 float* __restrict__ ctx) {
    __shared__ float ws[TCHUNK];
    const int b  = blockIdx.y;
    const int t0 = blockIdx.x * TCHUNK;
    const int tid = threadIdx.x;

    const float mx  = g_smax[b];
    const float inv = g_sinv[b];
    if (tid < TCHUNK) {
        float w = expf(g_logits[b * Tq + t0 + tid] - mx) * inv;
        ws[tid] = w;
        out_w[b * Tq + t0 + tid] = w;
    }
    __syncthreads();

    const int d4 = tid & 127;         // which float4 of the 512-wide row
    const int tp = tid >> 7;          // 0/1: t-interleave
    const float* fb = features + (long)b * Tq * Dq + (long)t0 * Dq + d4 * 4;
    float4 acc = make_float4(0.f, 0.f, 0.f, 0.f);
    #pragma unroll 8
    for (int i = tp; i < TCHUNK; i += 2) {
        float  wt = ws[i];
        float4 v  = *reinterpret_cast<const float4*>(fb + (long)i * Dq);
        acc.x = fmaf(wt, v.x, acc.x);
        acc.y = fmaf(wt, v.y, acc.y);
        acc.z = fmaf(wt, v.z, acc.z);
        acc.w = fmaf(wt, v.w, acc.w);
    }
    float* dst = ctx + b * Dq + d4 * 4;
    atomicAdd(dst + 0, acc.x);
    atomicAdd(dst + 1, acc.y);
    atomicAdd(dst + 2, acc.z);
    atomicAdd(dst + 3, acc.w);
}

// ---------------------------------------------------------------------------
extern "C" void kernel_launch(void* const* d_in, const int* in_sizes, int n_in,
                              void* d_out, int out_size) {
    const float* features = (const float*)d_in[0];  // [B,T,D]
    const float* hidden   = (const float*)d_in[1];  // [B,H]
    const float* Wk       = (const float*)d_in[2];  // [D,U]
    const float* Wb       = (const float*)d_in[3];  // [U]
    const float* Uk       = (const float*)d_in[4];  // [H,U]
    const float* Ub       = (const float*)d_in[5];  // [U]
    const float* Vk       = (const float*)d_in[6];  // [U,1]
    // d_in[7] = Vb [1]: uniform logit shift -> softmax-invariant -> unused.

    float* out  = (float*)d_out;
    float* ctx  = out;               // context_vector [B, D]  (tuple output 0)
    float* attw = out + Bq * Dq;     // attention_weights [B, T, 1] (tuple output 1)

    cudaFuncSetAttribute(logits_kernel,
                         cudaFuncAttributeMaxDynamicSharedMemorySize, SM_TOT);

    prep_kernel<<<768, 256>>>(hidden, Uk, Ub, Wb, Wk, ctx);
    logits_kernel<<<(Bq * Tq) / BM, 256, SM_TOT>>>(features, Vk);
    stats_kernel<<<Bq, 256>>>();
    ctxw_kernel<<<dim3(Tq / TCHUNK, Bq), 256>>>(features, attw, ctx);
}